// round 1
// baseline (speedup 1.0000x reference)
#include <cuda_runtime.h>
#include <cstdint>

// ---------------------------------------------------------------------------
// Problem constants
// ---------------------------------------------------------------------------
// B=16, T=64, N=49 (+1 audio node = 50), D=H=512, WIN=7
#define NEGBIG (-1e9f)

static const int BT       = 16 * 64;          // 1024 (b,t) pairs
static const int ROWS_ALL = BT * 50;          // 51200 node rows
static const int ROWS_TMP = 16 * 63 * 50;     // 50400 temporal rows
static const long long OUT_ELEMS  = (long long)ROWS_ALL * 512;  // 26,214,400
static const long long ATTN_ELEMS = (long long)BT * 2500;       //  2,560,000
static const long long COS_ELEMS  = (long long)ROWS_TMP;        //     50,400

// ---------------------------------------------------------------------------
// Device scratch (static — no allocations allowed)
// ---------------------------------------------------------------------------
__device__ float g_node[51200 * 512];
__device__ float g_spatial[51200 * 512];
__device__ float g_t1[51200 * 512];
__device__ float g_t2[51200 * 512];
__device__ float g_t3[51200 * 512];
__device__ float g_attn[1024 * 2500];
__device__ float g_cos[50400];

// ---------------------------------------------------------------------------
// concat(visual, audio) -> [51200, 512]
// ---------------------------------------------------------------------------
__global__ __launch_bounds__(256) void concat_kernel(
    const float* __restrict__ vis, const float* __restrict__ aud,
    float* __restrict__ out)
{
    long long idx = (long long)blockIdx.x * 256 + threadIdx.x;
    if (idx >= (long long)51200 * 128) return;
    long long r = idx >> 7;
    int hv = (int)(idx & 127);
    int bt = (int)(r / 50), i = (int)(r % 50);
    float4 v;
    if (i < 49)
        v = ((const float4*)vis)[((long long)bt * 49 + i) * 128 + hv];
    else
        v = ((const float4*)aud)[(long long)bt * 128 + hv];
    ((float4*)out)[idx] = v;
}

// ---------------------------------------------------------------------------
// Generic fp32 NT GEMM: C = epilogue(A[M,512] @ W[512,512]^T)
// mode 0: C[m,n] = acc + bias[n]
// mode 1: C[m,n] = relu(acc + bias[n])
// mode 2: temporal scatter:  g = row((b,tq+1,i));
//         C[g,n] = add2[g,n] + add1[m,n] + relu(acc + bias[n])
// mode 3: C[m,n] = add1[m,n] + relu(acc)
// ---------------------------------------------------------------------------
__global__ __launch_bounds__(256) void gemm_nt(
    const float* __restrict__ A, const float* __restrict__ W,
    const float* __restrict__ bias, const float* __restrict__ add1,
    const float* __restrict__ add2, float* __restrict__ C,
    int M, int mode)
{
    __shared__ float As[16][132];
    __shared__ float Bs[16][132];
    const int m0 = blockIdx.y * 128;
    const int n0 = blockIdx.x * 128;
    const int tid = threadIdx.x;
    const int ty = tid >> 4, tx = tid & 15;

    float acc[8][8];
#pragma unroll
    for (int u = 0; u < 8; u++)
#pragma unroll
        for (int v = 0; v < 8; v++) acc[u][v] = 0.f;

    for (int k0 = 0; k0 < 512; k0 += 16) {
#pragma unroll
        for (int l = 0; l < 2; l++) {
            int t = tid + l * 256;      // 0..511
            int r = t >> 2;             // 0..127
            int c4 = t & 3;             // float4 within k-tile
            float4 av = make_float4(0.f, 0.f, 0.f, 0.f);
            if (m0 + r < M)
                av = *(const float4*)(A + (long long)(m0 + r) * 512 + k0 + (c4 << 2));
            As[c4 * 4 + 0][r] = av.x; As[c4 * 4 + 1][r] = av.y;
            As[c4 * 4 + 2][r] = av.z; As[c4 * 4 + 3][r] = av.w;
            float4 wv = *(const float4*)(W + (long long)(n0 + r) * 512 + k0 + (c4 << 2));
            Bs[c4 * 4 + 0][r] = wv.x; Bs[c4 * 4 + 1][r] = wv.y;
            Bs[c4 * 4 + 2][r] = wv.z; Bs[c4 * 4 + 3][r] = wv.w;
        }
        __syncthreads();
#pragma unroll
        for (int kk = 0; kk < 16; kk++) {
            float a[8], b[8];
            *(float4*)(a)     = *(const float4*)&As[kk][ty * 8];
            *(float4*)(a + 4) = *(const float4*)&As[kk][ty * 8 + 4];
            *(float4*)(b)     = *(const float4*)&Bs[kk][tx * 8];
            *(float4*)(b + 4) = *(const float4*)&Bs[kk][tx * 8 + 4];
#pragma unroll
            for (int u = 0; u < 8; u++)
#pragma unroll
                for (int v = 0; v < 8; v++)
                    acc[u][v] = fmaf(a[u], b[v], acc[u][v]);
        }
        __syncthreads();
    }

    float bvals[8];
#pragma unroll
    for (int v = 0; v < 8; v++)
        bvals[v] = bias ? bias[n0 + tx * 8 + v] : 0.f;

#pragma unroll
    for (int u = 0; u < 8; u++) {
        int m = m0 + ty * 8 + u;
        if (m >= M) break;
        long long orow;
        if (mode == 2) {
            int b_ = m / 3150;
            int tq = (m / 50) % 63;
            int i_ = m % 50;
            orow = ((long long)(b_ * 64 + tq + 1) * 50 + i_) * 512;
        } else {
            orow = (long long)m * 512;
        }
        long long arow = (long long)m * 512;
#pragma unroll
        for (int v = 0; v < 8; v++) {
            int n = n0 + tx * 8 + v;
            float val = acc[u][v];
            float o;
            if (mode == 0)      o = val + bvals[v];
            else if (mode == 1) o = fmaxf(val + bvals[v], 0.f);
            else if (mode == 2) o = add2[orow + n] + add1[arow + n] + fmaxf(val + bvals[v], 0.f);
            else                o = add1[arow + n] + fmaxf(val, 0.f);
            C[orow + n] = o;
        }
    }
}

// ---------------------------------------------------------------------------
// Fused attention for one (b,t): Gram trick + mask + softmax + aggregation
// Writes pre-LN (spatial_agg + x) rows and the attention matrix.
// ---------------------------------------------------------------------------
#define ATTN_SMEM_FLOATS (52*512 + 3*512 + 52*52 + 6*52 + 8)

__global__ __launch_bounds__(256) void attn_kernel(
    const float* __restrict__ x, const float* __restrict__ edge,
    float* __restrict__ y_out, float* __restrict__ attn_out)
{
    extern __shared__ float sm[];
    float* xs  = sm;               // [52][512], rows 50/51 zero
    float* es  = xs + 52 * 512;    // [3][512]
    float* G   = es + 3 * 512;     // [52][52]
    float* rq  = G + 52 * 52;
    float* rk0 = rq + 52;
    float* rk1 = rk0 + 52;
    float* d0  = rk1 + 52;
    float* d1  = d0 + 52;
    float* d2  = d1 + 52;
    float* sc  = d2 + 52;          // E0,E1,E2, rk2

    const int bt = blockIdx.x;
    const int tid = threadIdx.x;
    const float* xg = x + (long long)bt * 50 * 512;

    for (int idx = tid; idx < 50 * 128; idx += 256)
        ((float4*)xs)[idx] = ((const float4*)xg)[idx];
    for (int idx = tid; idx < 2 * 128; idx += 256)
        ((float4*)xs)[50 * 128 + idx] = make_float4(0.f, 0.f, 0.f, 0.f);
    for (int idx = tid; idx < 3 * 128; idx += 256)
        ((float4*)es)[idx] = ((const float4*)edge)[idx];
    __syncthreads();

    // -------- Gram matrix G[i][j] = dot(x_i, x_j), 4x4 register tiles -----
    if (tid < 169) {
        int i0 = (tid / 13) * 4, j0 = (tid % 13) * 4;
        float acc[4][4];
#pragma unroll
        for (int u = 0; u < 4; u++)
#pragma unroll
            for (int v = 0; v < 4; v++) acc[u][v] = 0.f;
        const float4* xi0 = (const float4*)(xs + (i0 + 0) * 512);
        const float4* xi1 = (const float4*)(xs + (i0 + 1) * 512);
        const float4* xi2 = (const float4*)(xs + (i0 + 2) * 512);
        const float4* xi3 = (const float4*)(xs + (i0 + 3) * 512);
        const float4* xj0 = (const float4*)(xs + (j0 + 0) * 512);
        const float4* xj1 = (const float4*)(xs + (j0 + 1) * 512);
        const float4* xj2 = (const float4*)(xs + (j0 + 2) * 512);
        const float4* xj3 = (const float4*)(xs + (j0 + 3) * 512);
#pragma unroll 2
        for (int k = 0; k < 128; k++) {
            float4 A0 = xi0[k], A1 = xi1[k], A2 = xi2[k], A3 = xi3[k];
            float4 B0 = xj0[k], B1 = xj1[k], B2 = xj2[k], B3 = xj3[k];
#define GACC(u,v,Au,Bv) acc[u][v] += Au.x*Bv.x + Au.y*Bv.y + Au.z*Bv.z + Au.w*Bv.w;
            GACC(0,0,A0,B0) GACC(0,1,A0,B1) GACC(0,2,A0,B2) GACC(0,3,A0,B3)
            GACC(1,0,A1,B0) GACC(1,1,A1,B1) GACC(1,2,A1,B2) GACC(1,3,A1,B3)
            GACC(2,0,A2,B0) GACC(2,1,A2,B1) GACC(2,2,A2,B2) GACC(2,3,A2,B3)
            GACC(3,0,A3,B0) GACC(3,1,A3,B1) GACC(3,2,A3,B2) GACC(3,3,A3,B3)
#undef GACC
        }
#pragma unroll
        for (int u = 0; u < 4; u++)
#pragma unroll
            for (int v = 0; v < 4; v++)
                G[(i0 + u) * 52 + (j0 + v)] = acc[u][v];
    }
    __syncthreads();

    // -------- d_k[i] = dot(x_i, e_k), E_k = |e_k|^2 ------------------------
    if (tid < 150) {
        int kk = tid % 3, i = tid / 3;
        const float4* ev = (const float4*)(es + kk * 512);
        const float4* xv = (const float4*)(xs + i * 512);
        float s = 0.f;
        for (int k = 0; k < 128; k++) {
            float4 e4 = ev[k], x4 = xv[k];
            s += e4.x * x4.x + e4.y * x4.y + e4.z * x4.z + e4.w * x4.w;
        }
        (kk == 0 ? d0 : (kk == 1 ? d1 : d2))[i] = s;
    } else if (tid >= 160 && tid < 163) {
        int kk = tid - 160;
        const float4* ev = (const float4*)(es + kk * 512);
        float s = 0.f;
        for (int k = 0; k < 128; k++) {
            float4 e4 = ev[k];
            s += e4.x * e4.x + e4.y * e4.y + e4.z * e4.z + e4.w * e4.w;
        }
        sc[kk] = s;
    }
    __syncthreads();

    // -------- norms --------------------------------------------------------
    if (tid < 50) {
        float gd = G[tid * 53];
        rq[tid]  = 1.f / fmaxf(sqrtf(gd), 1e-12f);
        rk0[tid] = 1.f / fmaxf(sqrtf(gd + 2.f * d0[tid] + sc[0]), 1e-12f);
        rk1[tid] = 1.f / fmaxf(sqrtf(gd + 2.f * d1[tid] + sc[1]), 1e-12f);
    } else if (tid == 50) {
        sc[3] = 1.f / fmaxf(sqrtf(G[49 * 53] + 2.f * d2[49] + sc[2]), 1e-12f);
    }
    __syncthreads();

    const float rk2  = sc[3];
    const float d149 = d1[49];
    const float rq49 = rq[49];

    // -------- scores (in place, each element touched by one thread) -------
    for (int p = tid; p < 2500; p += 256) {
        int i = p / 50, j = p - i * 50;
        float v;
        if (i == j)        v = NEGBIG;
        else if (j == 49)  v = (G[i * 52 + 49] + d2[i]) * rq[i] * rk2;
        else if (i == 49)  v = (G[49 * 52 + j] + d149) * rq49 * rk1[j];
        else {
            int qr = i / 7, qc = i - qr * 7;
            int kr = j / 7, kc = j - kr * 7;
            int r0 = qr - 1; if (r0 < 0) r0 = 0;
            int c0 = qc - 1; if (c0 < 0) c0 = 0; if (c0 > 4) c0 = 4;
            bool ok = (kr >= r0) && (kr <= r0 + 2) && (kc >= c0) && (kc <= c0 + 2);
            v = ok ? (G[i * 52 + j] + d0[i]) * rq[i] * rk0[j] : NEGBIG;
        }
        G[i * 52 + j] = v;
    }
    __syncthreads();

    // -------- softmax per row ---------------------------------------------
    if (tid < 50) {
        float* row = G + tid * 52;
        float mx = -3.4e38f;
        for (int j = 0; j < 50; j++) mx = fmaxf(mx, row[j]);
        float s = 0.f;
        for (int j = 0; j < 50; j++) { float e = expf(row[j] - mx); row[j] = e; s += e; }
        float inv = 1.f / s;
        for (int j = 0; j < 50; j++) row[j] *= inv;
    }
    __syncthreads();

    // -------- write attention ---------------------------------------------
    for (int p = tid; p < 2500; p += 256)
        attn_out[(long long)bt * 2500 + p] = G[(p / 50) * 52 + (p % 50)];

    // -------- aggregation + edge correction + residual ---------------------
    // spatial[i] = sum_j a[i][j]*x_j + (1-a[i][49])*e_sel + a[i][49]*e2 + x_i
    for (int w = tid; w < 13 * 128; w += 256) {
        int it = w >> 7, hv = w & 127;
        int i0 = it * 4;
        float4 acc[4];
#pragma unroll
        for (int u = 0; u < 4; u++) acc[u] = make_float4(0.f, 0.f, 0.f, 0.f);
        for (int j = 0; j < 50; j++) {
            float4 xv = ((const float4*)(xs + j * 512))[hv];
            float a0 = G[(i0 + 0) * 52 + j];
            float a1 = G[(i0 + 1) * 52 + j];
            float a2 = G[(i0 + 2) * 52 + j];
            float a3 = G[(i0 + 3) * 52 + j];
            acc[0].x += a0 * xv.x; acc[0].y += a0 * xv.y; acc[0].z += a0 * xv.z; acc[0].w += a0 * xv.w;
            acc[1].x += a1 * xv.x; acc[1].y += a1 * xv.y; acc[1].z += a1 * xv.z; acc[1].w += a1 * xv.w;
            acc[2].x += a2 * xv.x; acc[2].y += a2 * xv.y; acc[2].z += a2 * xv.z; acc[2].w += a2 * xv.w;
            acc[3].x += a3 * xv.x; acc[3].y += a3 * xv.y; acc[3].z += a3 * xv.z; acc[3].w += a3 * xv.w;
        }
        float4 e2v = ((const float4*)(es + 1024))[hv];
#pragma unroll
        for (int u = 0; u < 4; u++) {
            int i = i0 + u;
            if (i >= 50) break;
            float aL = G[i * 52 + 49];
            float4 esel = ((const float4*)(es + (i < 49 ? 0 : 512)))[hv];
            float4 xr = ((const float4*)(xs + i * 512))[hv];
            float w1 = 1.f - aL;
            float4 o;
            o.x = acc[u].x + w1 * esel.x + aL * e2v.x + xr.x;
            o.y = acc[u].y + w1 * esel.y + aL * e2v.y + xr.y;
            o.z = acc[u].z + w1 * esel.z + aL * e2v.z + xr.z;
            o.w = acc[u].w + w1 * esel.w + aL * e2v.w + xr.w;
            ((float4*)(y_out + ((long long)bt * 50 + i) * 512))[hv] = o;
        }
    }
}

// ---------------------------------------------------------------------------
// LayerNorm (warp per 512-row) with optional relu
// ---------------------------------------------------------------------------
__global__ __launch_bounds__(256) void ln_kernel(
    const float* __restrict__ in, float* __restrict__ out,
    const float* __restrict__ g, const float* __restrict__ b,
    int rows, int do_relu)
{
    int warp = (blockIdx.x * 256 + threadIdx.x) >> 5;
    int lane = threadIdx.x & 31;
    if (warp >= rows) return;
    const float4* ip = (const float4*)(in + (long long)warp * 512);
    float4 v[4];
    float s = 0.f;
#pragma unroll
    for (int q = 0; q < 4; q++) {
        v[q] = ip[lane + 32 * q];
        s += v[q].x + v[q].y + v[q].z + v[q].w;
    }
#pragma unroll
    for (int off = 16; off; off >>= 1) s += __shfl_xor_sync(0xffffffffu, s, off);
    float mean = s * (1.f / 512.f);
    float ss = 0.f;
#pragma unroll
    for (int q = 0; q < 4; q++) {
        float dx = v[q].x - mean, dy = v[q].y - mean, dz = v[q].z - mean, dw = v[q].w - mean;
        ss += dx * dx + dy * dy + dz * dz + dw * dw;
    }
#pragma unroll
    for (int off = 16; off; off >>= 1) ss += __shfl_xor_sync(0xffffffffu, ss, off);
    float inv = rsqrtf(ss * (1.f / 512.f) + 1e-5f);
    float4* op = (float4*)(out + (long long)warp * 512);
    const float4* gp = (const float4*)g;
    const float4* bp = (const float4*)b;
#pragma unroll
    for (int q = 0; q < 4; q++) {
        int c = lane + 32 * q;
        float4 gv = gp[c], bv = bp[c], o;
        o.x = (v[q].x - mean) * inv * gv.x + bv.x;
        o.y = (v[q].y - mean) * inv * gv.y + bv.y;
        o.z = (v[q].z - mean) * inv * gv.z + bv.z;
        o.w = (v[q].w - mean) * inv * gv.w + bv.w;
        if (do_relu) {
            o.x = fmaxf(o.x, 0.f); o.y = fmaxf(o.y, 0.f);
            o.z = fmaxf(o.z, 0.f); o.w = fmaxf(o.w, 0.f);
        }
        op[c] = o;
    }
}

// ---------------------------------------------------------------------------
// cos similarity between consecutive timesteps + build GEMM inputs
// Ac[m] = cos * prev,  As[m] = (1-cos) * cur
// ---------------------------------------------------------------------------
__global__ __launch_bounds__(256) void cos_kernel(
    const float* __restrict__ spatial, float* __restrict__ cosv,
    float* __restrict__ Ac, float* __restrict__ As)
{
    int warp = (blockIdx.x * 256 + threadIdx.x) >> 5;
    int lane = threadIdx.x & 31;
    if (warp >= 50400) return;
    int i = warp % 50;
    int tq = (warp / 50) % 63;
    int b_ = warp / 3150;
    long long cur_off  = (((long long)b_ * 64 + tq + 1) * 50 + i) * 512;
    long long prev_off = (((long long)b_ * 64 + tq) * 50 + i) * 512;
    const float4* cp = (const float4*)(spatial + cur_off);
    const float4* pp = (const float4*)(spatial + prev_off);
    float4 cb[4], pb[4];
    float dt = 0.f, na = 0.f, nb = 0.f;
#pragma unroll
    for (int q = 0; q < 4; q++) {
        cb[q] = cp[lane + 32 * q];
        pb[q] = pp[lane + 32 * q];
        dt += cb[q].x * pb[q].x + cb[q].y * pb[q].y + cb[q].z * pb[q].z + cb[q].w * pb[q].w;
        na += cb[q].x * cb[q].x + cb[q].y * cb[q].y + cb[q].z * cb[q].z + cb[q].w * cb[q].w;
        nb += pb[q].x * pb[q].x + pb[q].y * pb[q].y + pb[q].z * pb[q].z + pb[q].w * pb[q].w;
    }
#pragma unroll
    for (int off = 16; off; off >>= 1) {
        dt += __shfl_xor_sync(0xffffffffu, dt, off);
        na += __shfl_xor_sync(0xffffffffu, na, off);
        nb += __shfl_xor_sync(0xffffffffu, nb, off);
    }
    float cv = dt / (fmaxf(sqrtf(na), 1e-8f) * fmaxf(sqrtf(nb), 1e-8f));
    if (lane == 0) cosv[warp] = cv;
    float4* acp = (float4*)(Ac + (long long)warp * 512);
    float4* asp = (float4*)(As + (long long)warp * 512);
    float w1 = 1.f - cv;
#pragma unroll
    for (int q = 0; q < 4; q++) {
        int c = lane + 32 * q;
        float4 a, s;
        a.x = cv * pb[q].x; a.y = cv * pb[q].y; a.z = cv * pb[q].z; a.w = cv * pb[q].w;
        s.x = w1 * cb[q].x; s.y = w1 * cb[q].y; s.z = w1 * cb[q].z; s.w = w1 * cb[q].w;
        acp[c] = a;
        asp[c] = s;
    }
}

// ---------------------------------------------------------------------------
// copy t=0 rows of spatial into out_pre buffer
// ---------------------------------------------------------------------------
__global__ __launch_bounds__(256) void copy_t0_kernel(
    const float* __restrict__ src, float* __restrict__ dst)
{
    int idx = blockIdx.x * 256 + threadIdx.x;     // 800 rows * 128 float4
    if (idx >= 800 * 128) return;
    int r = idx >> 7, hv = idx & 127;
    int b_ = r / 50, i = r % 50;
    long long row = ((long long)b_ * 64) * 50 + i;
    ((float4*)(dst + row * 512))[hv] = ((const float4*)(src + row * 512))[hv];
}

// ---------------------------------------------------------------------------
// Host launcher
// ---------------------------------------------------------------------------
extern "C" void kernel_launch(void* const* d_in, const int* in_sizes, int n_in,
                              void* d_out, int out_size)
{
    const float* visual = (const float*)d_in[0];
    const float* audio  = (const float*)d_in[1];
    const float* in_W   = (const float*)d_in[2];
    const float* in_b   = (const float*)d_in[3];
    const float* out_W  = (const float*)d_in[4];
    const float* out_b  = (const float*)d_in[5];

    float *node, *spatial, *t1, *t2, *t3, *attnb, *cosb;
    cudaGetSymbolAddress((void**)&node,    g_node);
    cudaGetSymbolAddress((void**)&spatial, g_spatial);
    cudaGetSymbolAddress((void**)&t1,      g_t1);
    cudaGetSymbolAddress((void**)&t2,      g_t2);
    cudaGetSymbolAddress((void**)&t3,      g_t3);
    cudaGetSymbolAddress((void**)&attnb,   g_attn);
    cudaGetSymbolAddress((void**)&cosb,    g_cos);

    const int smem_attn = ATTN_SMEM_FLOATS * 4;
    cudaFuncSetAttribute(attn_kernel,
                         cudaFuncAttributeMaxDynamicSharedMemorySize, smem_attn);

    // input concat + projection
    concat_kernel<<<25600, 256>>>(visual, audio, t1);
    dim3 gAll(4, (51200 + 127) / 128);   // (4, 400)
    dim3 gTmp(4, (50400 + 127) / 128);   // (4, 394)
    gemm_nt<<<gAll, 256>>>(t1, in_W, in_b, nullptr, nullptr, node, 51200, 0);

    for (int L = 0; L < 2; L++) {
        int base = 6 + L * 8;
        const float* edge = (const float*)d_in[base + 0];
        const float* lng  = (const float*)d_in[base + 1];
        const float* lnb  = (const float*)d_in[base + 2];
        const float* Wc   = (const float*)d_in[base + 3];
        const float* bc   = (const float*)d_in[base + 4];
        const float* Ws   = (const float*)d_in[base + 5];
        const float* bs   = (const float*)d_in[base + 6];
        const float* Wo   = (const float*)d_in[base + 7];

        // spatial attention (pre-LN result -> t2, attn -> attnb)
        attn_kernel<<<1024, 256, smem_attn>>>(node, edge, t2, attnb);
        // spatial = relu(LN(t2))
        ln_kernel<<<51200 / 8, 256>>>(t2, spatial, lng, lnb, 51200, 1);
        // cos + temporal GEMM inputs (Ac -> t2, As -> t3)
        cos_kernel<<<6300, 256>>>(spatial, cosb, t2, t3);
        // Rc = relu(Ac @ Wc^T + bc) -> t1
        gemm_nt<<<gTmp, 256>>>(t2, Wc, bc, nullptr, nullptr, t1, 50400, 1);
        // out_pre[t>=1] = cur + Rc + relu(As @ Ws^T + bs)  (scatter) -> t2
        gemm_nt<<<gTmp, 256>>>(t3, Ws, bs, t1, spatial, t2, 50400, 2);
        // out_pre[t=0] = spatial[t=0]
        copy_t0_kernel<<<400, 256>>>(spatial, t2);
        // ln_out = LN(out_pre) -> t3
        ln_kernel<<<51200 / 8, 256>>>(t2, t3, lng, lnb, 51200, 0);
        // node = node + relu(ln_out @ Wo^T)
        gemm_nt<<<gAll, 256>>>(t3, Wo, nullptr, node, nullptr, node, 51200, 3);
    }

    // final projection directly into d_out
    gemm_nt<<<gAll, 256>>>(node, out_W, out_b, nullptr, nullptr,
                           (float*)d_out, 51200, 0);

    // auxiliary outputs (attn of last layer, cos of last layer)
    long long need = OUT_ELEMS + ATTN_ELEMS + COS_ELEMS;
    if ((long long)out_size >= need) {
        cudaMemcpyAsync((float*)d_out + OUT_ELEMS, attnb,
                        ATTN_ELEMS * sizeof(float), cudaMemcpyDeviceToDevice);
        cudaMemcpyAsync((float*)d_out + OUT_ELEMS + ATTN_ELEMS, cosb,
                        COS_ELEMS * sizeof(float), cudaMemcpyDeviceToDevice);
    }
}

// round 2
// speedup vs baseline: 1.7440x; 1.7440x over previous
#include <cuda_runtime.h>
#include <cstdint>

// ---------------------------------------------------------------------------
// Problem constants: B=16, T=64, N=49 (+1 audio = 50), D=H=512, WIN=7
// ---------------------------------------------------------------------------
#define NEGBIG (-1e9f)

static const int BT       = 16 * 64;          // 1024
static const int ROWS_ALL = BT * 50;          // 51200
static const int ROWS_TMP = 16 * 63 * 50;     // 50400
static const long long OUT_ELEMS  = (long long)ROWS_ALL * 512;
static const long long ATTN_ELEMS = (long long)BT * 2500;
static const long long COS_ELEMS  = (long long)ROWS_TMP;

// ---------------------------------------------------------------------------
// Device scratch (static — no allocations allowed)
// ---------------------------------------------------------------------------
__device__ float g_node[51200 * 512];
__device__ float g_spatial[51200 * 512];
__device__ float g_t1[51200 * 512];
__device__ float g_t2[51200 * 512];
__device__ float g_t3[51200 * 512];
__device__ float g_attn[1024 * 2500];
__device__ float g_cos[50400];

// ---------------------------------------------------------------------------
// concat(visual, audio) -> [51200, 512]
// ---------------------------------------------------------------------------
__global__ __launch_bounds__(256) void concat_kernel(
    const float* __restrict__ vis, const float* __restrict__ aud,
    float* __restrict__ out)
{
    long long idx = (long long)blockIdx.x * 256 + threadIdx.x;
    if (idx >= (long long)51200 * 128) return;
    long long r = idx >> 7;
    int hv = (int)(idx & 127);
    int bt = (int)(r / 50), i = (int)(r % 50);
    float4 v;
    if (i < 49)
        v = ((const float4*)vis)[((long long)bt * 49 + i) * 128 + hv];
    else
        v = ((const float4*)aud)[(long long)bt * 128 + hv];
    ((float4*)out)[idx] = v;
}

// ---------------------------------------------------------------------------
// tf32 tensor-core NT GEMM: C = epilogue(A[M,512] @ W[512,512]^T)
// Tile 128x128x32, 8 warps, warp tile 64x32, mma.m16n8k8.tf32.
// mode 0: C = acc + bias
// mode 1: C = relu(acc + bias)
// mode 2: scatter g=row(b,tq+1,i): C[g] = add2[g] + add1[m] + relu(acc+bias)
// mode 3: C = add1[m] + relu(acc)
// ---------------------------------------------------------------------------
#define GBK 32
#define GPAD 136   // floats per smem k-row (conflict-free fragment loads)
#define GBUF (GBK * GPAD)

__device__ __forceinline__ uint32_t f2tf32(float x) {
    uint32_t r;
    asm("cvt.rna.tf32.f32 %0, %1;" : "=r"(r) : "f"(x));
    return r;
}

__device__ __forceinline__ void mma_tf32(
    float c[4], uint32_t a0, uint32_t a1, uint32_t a2, uint32_t a3,
    uint32_t b0, uint32_t b1)
{
    asm volatile(
        "mma.sync.aligned.m16n8k8.row.col.f32.tf32.tf32.f32 "
        "{%0,%1,%2,%3}, {%4,%5,%6,%7}, {%8,%9}, {%0,%1,%2,%3};\n"
        : "+f"(c[0]), "+f"(c[1]), "+f"(c[2]), "+f"(c[3])
        : "r"(a0), "r"(a1), "r"(a2), "r"(a3), "r"(b0), "r"(b1));
}

__global__ __launch_bounds__(256) void gemm_tf32(
    const float* __restrict__ A, const float* __restrict__ W,
    const float* __restrict__ bias, const float* __restrict__ add1,
    const float* __restrict__ add2, float* __restrict__ C,
    int M, int mode)
{
    extern __shared__ uint32_t smem_u[];
    // layout: As buf0 | As buf1 | Bs buf0 | Bs buf1, each GBUF u32
    uint32_t* AsBase = smem_u;
    uint32_t* BsBase = smem_u + 2 * GBUF;

    const int m0 = blockIdx.y * 128;
    const int n0 = blockIdx.x * 128;
    const int tid = threadIdx.x;
    const int wid = tid >> 5, lane = tid & 31;
    const int wm = wid >> 2, wn = wid & 3;      // warp grid 2x4
    const int g = lane >> 2, t = lane & 3;

    // global staging mapping: 2 threads per tile row, 16 k each
    const int lr = tid >> 1;
    const int lk = (tid & 1) << 4;
    const bool arow_ok = (m0 + lr) < M;
    const float* aRow = A + (long long)(m0 + lr) * 512 + lk;
    const float* wRow = W + (long long)(n0 + lr) * 512 + lk;

    float acc[4][4][4];
#pragma unroll
    for (int mf = 0; mf < 4; mf++)
#pragma unroll
        for (int nf = 0; nf < 4; nf++)
#pragma unroll
            for (int q = 0; q < 4; q++) acc[mf][nf][q] = 0.f;

    uint32_t sa[16], sb[16];

    // --- load k-tile kt into staging regs (with tf32 rounding) ---
    auto LDG = [&](int kt) {
        const int k0 = kt * GBK;
#pragma unroll
        for (int i = 0; i < 4; i++) {
            float4 a4 = arow_ok ? *(const float4*)(aRow + k0 + i * 4)
                                : make_float4(0.f, 0.f, 0.f, 0.f);
            float4 b4 = *(const float4*)(wRow + k0 + i * 4);
            sa[i * 4 + 0] = f2tf32(a4.x); sa[i * 4 + 1] = f2tf32(a4.y);
            sa[i * 4 + 2] = f2tf32(a4.z); sa[i * 4 + 3] = f2tf32(a4.w);
            sb[i * 4 + 0] = f2tf32(b4.x); sb[i * 4 + 1] = f2tf32(b4.y);
            sb[i * 4 + 2] = f2tf32(b4.z); sb[i * 4 + 3] = f2tf32(b4.w);
        }
    };
    auto STS = [&](int buf) {
        uint32_t* as = AsBase + buf * GBUF;
        uint32_t* bs = BsBase + buf * GBUF;
#pragma unroll
        for (int i = 0; i < 16; i++) {
            as[(lk + i) * GPAD + lr] = sa[i];
            bs[(lk + i) * GPAD + lr] = sb[i];
        }
    };

    LDG(0);
    STS(0);
    __syncthreads();

    for (int kt = 0; kt < 16; kt++) {
        if (kt < 15) LDG(kt + 1);

        const uint32_t* as = AsBase + (kt & 1) * GBUF;
        const uint32_t* bs = BsBase + (kt & 1) * GBUF;
#pragma unroll
        for (int ks = 0; ks < 4; ks++) {
            const int kk = ks * 8;
            uint32_t af[4][4], bf[4][2];
#pragma unroll
            for (int mf = 0; mf < 4; mf++) {
                int m = wm * 64 + mf * 16;
                af[mf][0] = as[(kk + t) * GPAD + m + g];
                af[mf][1] = as[(kk + t) * GPAD + m + g + 8];
                af[mf][2] = as[(kk + t + 4) * GPAD + m + g];
                af[mf][3] = as[(kk + t + 4) * GPAD + m + g + 8];
            }
#pragma unroll
            for (int nf = 0; nf < 4; nf++) {
                int n = wn * 32 + nf * 8;
                bf[nf][0] = bs[(kk + t) * GPAD + n + g];
                bf[nf][1] = bs[(kk + t + 4) * GPAD + n + g];
            }
#pragma unroll
            for (int mf = 0; mf < 4; mf++)
#pragma unroll
                for (int nf = 0; nf < 4; nf++)
                    mma_tf32(acc[mf][nf], af[mf][0], af[mf][1], af[mf][2],
                             af[mf][3], bf[nf][0], bf[nf][1]);
        }

        if (kt < 15) {
            STS((kt + 1) & 1);
            __syncthreads();
        }
    }

    // ---------------- epilogue ----------------
#pragma unroll
    for (int mf = 0; mf < 4; mf++) {
#pragma unroll
        for (int half = 0; half < 2; half++) {
            int m = m0 + wm * 64 + mf * 16 + g + half * 8;
            if (m >= M) continue;
            long long orow;
            if (mode == 2) {
                int b_ = m / 3150;
                int tq = (m / 50) % 63;
                int i_ = m % 50;
                orow = ((long long)(b_ * 64 + tq + 1) * 50 + i_) * 512;
            } else {
                orow = (long long)m * 512;
            }
            long long arow = (long long)m * 512;
#pragma unroll
            for (int nf = 0; nf < 4; nf++) {
                int n = n0 + wn * 32 + nf * 8 + t * 2;
                float v0 = acc[mf][nf][half * 2 + 0];
                float v1 = acc[mf][nf][half * 2 + 1];
                float o0, o1;
                if (mode == 0) {
                    o0 = v0 + bias[n]; o1 = v1 + bias[n + 1];
                } else if (mode == 1) {
                    o0 = fmaxf(v0 + bias[n], 0.f);
                    o1 = fmaxf(v1 + bias[n + 1], 0.f);
                } else if (mode == 2) {
                    o0 = add2[orow + n]     + add1[arow + n]     + fmaxf(v0 + bias[n], 0.f);
                    o1 = add2[orow + n + 1] + add1[arow + n + 1] + fmaxf(v1 + bias[n + 1], 0.f);
                } else {
                    o0 = add1[arow + n]     + fmaxf(v0, 0.f);
                    o1 = add1[arow + n + 1] + fmaxf(v1, 0.f);
                }
                *(float2*)(C + orow + n) = make_float2(o0, o1);
            }
        }
    }
}

// ---------------------------------------------------------------------------
// Fused attention for one (b,t): Gram trick + mask + softmax + aggregation
// ---------------------------------------------------------------------------
#define ATTN_SMEM_FLOATS (52*512 + 3*512 + 52*52 + 6*52 + 8)

__global__ __launch_bounds__(256) void attn_kernel(
    const float* __restrict__ x, const float* __restrict__ edge,
    float* __restrict__ y_out, float* __restrict__ attn_out)
{
    extern __shared__ float sm[];
    float* xs  = sm;               // [52][512], rows 50/51 zero
    float* es  = xs + 52 * 512;    // [3][512]
    float* G   = es + 3 * 512;     // [52][52]
    float* rq  = G + 52 * 52;
    float* rk0 = rq + 52;
    float* rk1 = rk0 + 52;
    float* d0  = rk1 + 52;
    float* d1  = d0 + 52;
    float* d2  = d1 + 52;
    float* sc  = d2 + 52;

    const int bt = blockIdx.x;
    const int tid = threadIdx.x;
    const float* xg = x + (long long)bt * 50 * 512;

    for (int idx = tid; idx < 50 * 128; idx += 256)
        ((float4*)xs)[idx] = ((const float4*)xg)[idx];
    for (int idx = tid; idx < 2 * 128; idx += 256)
        ((float4*)xs)[50 * 128 + idx] = make_float4(0.f, 0.f, 0.f, 0.f);
    for (int idx = tid; idx < 3 * 128; idx += 256)
        ((float4*)es)[idx] = ((const float4*)edge)[idx];
    __syncthreads();

    if (tid < 169) {
        int i0 = (tid / 13) * 4, j0 = (tid % 13) * 4;
        float acc[4][4];
#pragma unroll
        for (int u = 0; u < 4; u++)
#pragma unroll
            for (int v = 0; v < 4; v++) acc[u][v] = 0.f;
        const float4* xi0 = (const float4*)(xs + (i0 + 0) * 512);
        const float4* xi1 = (const float4*)(xs + (i0 + 1) * 512);
        const float4* xi2 = (const float4*)(xs + (i0 + 2) * 512);
        const float4* xi3 = (const float4*)(xs + (i0 + 3) * 512);
        const float4* xj0 = (const float4*)(xs + (j0 + 0) * 512);
        const float4* xj1 = (const float4*)(xs + (j0 + 1) * 512);
        const float4* xj2 = (const float4*)(xs + (j0 + 2) * 512);
        const float4* xj3 = (const float4*)(xs + (j0 + 3) * 512);
#pragma unroll 2
        for (int k = 0; k < 128; k++) {
            float4 A0 = xi0[k], A1 = xi1[k], A2 = xi2[k], A3 = xi3[k];
            float4 B0 = xj0[k], B1 = xj1[k], B2 = xj2[k], B3 = xj3[k];
#define GACC(u,v,Au,Bv) acc[u][v] += Au.x*Bv.x + Au.y*Bv.y + Au.z*Bv.z + Au.w*Bv.w;
            GACC(0,0,A0,B0) GACC(0,1,A0,B1) GACC(0,2,A0,B2) GACC(0,3,A0,B3)
            GACC(1,0,A1,B0) GACC(1,1,A1,B1) GACC(1,2,A1,B2) GACC(1,3,A1,B3)
            GACC(2,0,A2,B0) GACC(2,1,A2,B1) GACC(2,2,A2,B2) GACC(2,3,A2,B3)
            GACC(3,0,A3,B0) GACC(3,1,A3,B1) GACC(3,2,A3,B2) GACC(3,3,A3,B3)
#undef GACC
        }
#pragma unroll
        for (int u = 0; u < 4; u++)
#pragma unroll
            for (int v = 0; v < 4; v++)
                G[(i0 + u) * 52 + (j0 + v)] = acc[u][v];
    }
    __syncthreads();

    if (tid < 150) {
        int kk = tid % 3, i = tid / 3;
        const float4* ev = (const float4*)(es + kk * 512);
        const float4* xv = (const float4*)(xs + i * 512);
        float s = 0.f;
        for (int k = 0; k < 128; k++) {
            float4 e4 = ev[k], x4 = xv[k];
            s += e4.x * x4.x + e4.y * x4.y + e4.z * x4.z + e4.w * x4.w;
        }
        (kk == 0 ? d0 : (kk == 1 ? d1 : d2))[i] = s;
    } else if (tid >= 160 && tid < 163) {
        int kk = tid - 160;
        const float4* ev = (const float4*)(es + kk * 512);
        float s = 0.f;
        for (int k = 0; k < 128; k++) {
            float4 e4 = ev[k];
            s += e4.x * e4.x + e4.y * e4.y + e4.z * e4.z + e4.w * e4.w;
        }
        sc[kk] = s;
    }
    __syncthreads();

    if (tid < 50) {
        float gd = G[tid * 53];
        rq[tid]  = 1.f / fmaxf(sqrtf(gd), 1e-12f);
        rk0[tid] = 1.f / fmaxf(sqrtf(gd + 2.f * d0[tid] + sc[0]), 1e-12f);
        rk1[tid] = 1.f / fmaxf(sqrtf(gd + 2.f * d1[tid] + sc[1]), 1e-12f);
    } else if (tid == 50) {
        sc[3] = 1.f / fmaxf(sqrtf(G[49 * 53] + 2.f * d2[49] + sc[2]), 1e-12f);
    }
    __syncthreads();

    const float rk2  = sc[3];
    const float d149 = d1[49];
    const float rq49 = rq[49];

    for (int p = tid; p < 2500; p += 256) {
        int i = p / 50, j = p - i * 50;
        float v;
        if (i == j)        v = NEGBIG;
        else if (j == 49)  v = (G[i * 52 + 49] + d2[i]) * rq[i] * rk2;
        else if (i == 49)  v = (G[49 * 52 + j] + d149) * rq49 * rk1[j];
        else {
            int qr = i / 7, qc = i - qr * 7;
            int kr = j / 7, kc = j - kr * 7;
            int r0 = qr - 1; if (r0 < 0) r0 = 0;
            int c0 = qc - 1; if (c0 < 0) c0 = 0; if (c0 > 4) c0 = 4;
            bool ok = (kr >= r0) && (kr <= r0 + 2) && (kc >= c0) && (kc <= c0 + 2);
            v = ok ? (G[i * 52 + j] + d0[i]) * rq[i] * rk0[j] : NEGBIG;
        }
        G[i * 52 + j] = v;
    }
    __syncthreads();

    if (tid < 50) {
        float* row = G + tid * 52;
        float mx = -3.4e38f;
        for (int j = 0; j < 50; j++) mx = fmaxf(mx, row[j]);
        float s = 0.f;
        for (int j = 0; j < 50; j++) { float e = expf(row[j] - mx); row[j] = e; s += e; }
        float inv = 1.f / s;
        for (int j = 0; j < 50; j++) row[j] *= inv;
    }
    __syncthreads();

    for (int p = tid; p < 2500; p += 256)
        attn_out[(long long)bt * 2500 + p] = G[(p / 50) * 52 + (p % 50)];

    for (int w = tid; w < 13 * 128; w += 256) {
        int it = w >> 7, hv = w & 127;
        int i0 = it * 4;
        float4 acc[4];
#pragma unroll
        for (int u = 0; u < 4; u++) acc[u] = make_float4(0.f, 0.f, 0.f, 0.f);
        for (int j = 0; j < 50; j++) {
            float4 xv = ((const float4*)(xs + j * 512))[hv];
            float a0 = G[(i0 + 0) * 52 + j];
            float a1 = G[(i0 + 1) * 52 + j];
            float a2 = G[(i0 + 2) * 52 + j];
            float a3 = G[(i0 + 3) * 52 + j];
            acc[0].x += a0 * xv.x; acc[0].y += a0 * xv.y; acc[0].z += a0 * xv.z; acc[0].w += a0 * xv.w;
            acc[1].x += a1 * xv.x; acc[1].y += a1 * xv.y; acc[1].z += a1 * xv.z; acc[1].w += a1 * xv.w;
            acc[2].x += a2 * xv.x; acc[2].y += a2 * xv.y; acc[2].z += a2 * xv.z; acc[2].w += a2 * xv.w;
            acc[3].x += a3 * xv.x; acc[3].y += a3 * xv.y; acc[3].z += a3 * xv.z; acc[3].w += a3 * xv.w;
        }
        float4 e2v = ((const float4*)(es + 1024))[hv];
#pragma unroll
        for (int u = 0; u < 4; u++) {
            int i = i0 + u;
            if (i >= 50) break;
            float aL = G[i * 52 + 49];
            float4 esel = ((const float4*)(es + (i < 49 ? 0 : 512)))[hv];
            float4 xr = ((const float4*)(xs + i * 512))[hv];
            float w1 = 1.f - aL;
            float4 o;
            o.x = acc[u].x + w1 * esel.x + aL * e2v.x + xr.x;
            o.y = acc[u].y + w1 * esel.y + aL * e2v.y + xr.y;
            o.z = acc[u].z + w1 * esel.z + aL * e2v.z + xr.z;
            o.w = acc[u].w + w1 * esel.w + aL * e2v.w + xr.w;
            ((float4*)(y_out + ((long long)bt * 50 + i) * 512))[hv] = o;
        }
    }
}

// ---------------------------------------------------------------------------
// LayerNorm (warp per 512-row) with optional relu
// ---------------------------------------------------------------------------
__global__ __launch_bounds__(256) void ln_kernel(
    const float* __restrict__ in, float* __restrict__ out,
    const float* __restrict__ g, const float* __restrict__ b,
    int rows, int do_relu)
{
    int warp = (blockIdx.x * 256 + threadIdx.x) >> 5;
    int lane = threadIdx.x & 31;
    if (warp >= rows) return;
    const float4* ip = (const float4*)(in + (long long)warp * 512);
    float4 v[4];
    float s = 0.f;
#pragma unroll
    for (int q = 0; q < 4; q++) {
        v[q] = ip[lane + 32 * q];
        s += v[q].x + v[q].y + v[q].z + v[q].w;
    }
#pragma unroll
    for (int off = 16; off; off >>= 1) s += __shfl_xor_sync(0xffffffffu, s, off);
    float mean = s * (1.f / 512.f);
    float ss = 0.f;
#pragma unroll
    for (int q = 0; q < 4; q++) {
        float dx = v[q].x - mean, dy = v[q].y - mean, dz = v[q].z - mean, dw = v[q].w - mean;
        ss += dx * dx + dy * dy + dz * dz + dw * dw;
    }
#pragma unroll
    for (int off = 16; off; off >>= 1) ss += __shfl_xor_sync(0xffffffffu, ss, off);
    float inv = rsqrtf(ss * (1.f / 512.f) + 1e-5f);
    float4* op = (float4*)(out + (long long)warp * 512);
    const float4* gp = (const float4*)g;
    const float4* bp = (const float4*)b;
#pragma unroll
    for (int q = 0; q < 4; q++) {
        int c = lane + 32 * q;
        float4 gv = gp[c], bv = bp[c], o;
        o.x = (v[q].x - mean) * inv * gv.x + bv.x;
        o.y = (v[q].y - mean) * inv * gv.y + bv.y;
        o.z = (v[q].z - mean) * inv * gv.z + bv.z;
        o.w = (v[q].w - mean) * inv * gv.w + bv.w;
        if (do_relu) {
            o.x = fmaxf(o.x, 0.f); o.y = fmaxf(o.y, 0.f);
            o.z = fmaxf(o.z, 0.f); o.w = fmaxf(o.w, 0.f);
        }
        op[c] = o;
    }
}

// ---------------------------------------------------------------------------
// cos similarity between consecutive timesteps + build GEMM inputs
// ---------------------------------------------------------------------------
__global__ __launch_bounds__(256) void cos_kernel(
    const float* __restrict__ spatial, float* __restrict__ cosv,
    float* __restrict__ Ac, float* __restrict__ As)
{
    int warp = (blockIdx.x * 256 + threadIdx.x) >> 5;
    int lane = threadIdx.x & 31;
    if (warp >= 50400) return;
    int i = warp % 50;
    int tq = (warp / 50) % 63;
    int b_ = warp / 3150;
    long long cur_off  = (((long long)b_ * 64 + tq + 1) * 50 + i) * 512;
    long long prev_off = (((long long)b_ * 64 + tq) * 50 + i) * 512;
    const float4* cp = (const float4*)(spatial + cur_off);
    const float4* pp = (const float4*)(spatial + prev_off);
    float4 cb[4], pb[4];
    float dt = 0.f, na = 0.f, nb = 0.f;
#pragma unroll
    for (int q = 0; q < 4; q++) {
        cb[q] = cp[lane + 32 * q];
        pb[q] = pp[lane + 32 * q];
        dt += cb[q].x * pb[q].x + cb[q].y * pb[q].y + cb[q].z * pb[q].z + cb[q].w * pb[q].w;
        na += cb[q].x * cb[q].x + cb[q].y * cb[q].y + cb[q].z * cb[q].z + cb[q].w * cb[q].w;
        nb += pb[q].x * pb[q].x + pb[q].y * pb[q].y + pb[q].z * pb[q].z + pb[q].w * pb[q].w;
    }
#pragma unroll
    for (int off = 16; off; off >>= 1) {
        dt += __shfl_xor_sync(0xffffffffu, dt, off);
        na += __shfl_xor_sync(0xffffffffu, na, off);
        nb += __shfl_xor_sync(0xffffffffu, nb, off);
    }
    float cv = dt / (fmaxf(sqrtf(na), 1e-8f) * fmaxf(sqrtf(nb), 1e-8f));
    if (lane == 0) cosv[warp] = cv;
    float4* acp = (float4*)(Ac + (long long)warp * 512);
    float4* asp = (float4*)(As + (long long)warp * 512);
    float w1 = 1.f - cv;
#pragma unroll
    for (int q = 0; q < 4; q++) {
        int c = lane + 32 * q;
        float4 a, s;
        a.x = cv * pb[q].x; a.y = cv * pb[q].y; a.z = cv * pb[q].z; a.w = cv * pb[q].w;
        s.x = w1 * cb[q].x; s.y = w1 * cb[q].y; s.z = w1 * cb[q].z; s.w = w1 * cb[q].w;
        acp[c] = a;
        asp[c] = s;
    }
}

// ---------------------------------------------------------------------------
// copy t=0 rows of spatial into out_pre buffer
// ---------------------------------------------------------------------------
__global__ __launch_bounds__(256) void copy_t0_kernel(
    const float* __restrict__ src, float* __restrict__ dst)
{
    int idx = blockIdx.x * 256 + threadIdx.x;
    if (idx >= 800 * 128) return;
    int r = idx >> 7, hv = idx & 127;
    int b_ = r / 50, i = r % 50;
    long long row = ((long long)b_ * 64) * 50 + i;
    ((float4*)(dst + row * 512))[hv] = ((const float4*)(src + row * 512))[hv];
}

// ---------------------------------------------------------------------------
// Host launcher
// ---------------------------------------------------------------------------
extern "C" void kernel_launch(void* const* d_in, const int* in_sizes, int n_in,
                              void* d_out, int out_size)
{
    const float* visual = (const float*)d_in[0];
    const float* audio  = (const float*)d_in[1];
    const float* in_W   = (const float*)d_in[2];
    const float* in_b   = (const float*)d_in[3];
    const float* out_W  = (const float*)d_in[4];
    const float* out_b  = (const float*)d_in[5];

    float *node, *spatial, *t1, *t2, *t3, *attnb, *cosb;
    cudaGetSymbolAddress((void**)&node,    g_node);
    cudaGetSymbolAddress((void**)&spatial, g_spatial);
    cudaGetSymbolAddress((void**)&t1,      g_t1);
    cudaGetSymbolAddress((void**)&t2,      g_t2);
    cudaGetSymbolAddress((void**)&t3,      g_t3);
    cudaGetSymbolAddress((void**)&attnb,   g_attn);
    cudaGetSymbolAddress((void**)&cosb,    g_cos);

    const int smem_attn = ATTN_SMEM_FLOATS * 4;
    cudaFuncSetAttribute(attn_kernel,
                         cudaFuncAttributeMaxDynamicSharedMemorySize, smem_attn);
    const int smem_gemm = 4 * GBUF * 4;   // 69632 bytes
    cudaFuncSetAttribute(gemm_tf32,
                         cudaFuncAttributeMaxDynamicSharedMemorySize, smem_gemm);

    concat_kernel<<<25600, 256>>>(visual, audio, t1);
    dim3 gAll(4, 400);                    // 51200 rows
    dim3 gTmp(4, (50400 + 127) / 128);    // 394
    gemm_tf32<<<gAll, 256, smem_gemm>>>(t1, in_W, in_b, nullptr, nullptr,
                                        node, 51200, 0);

    for (int L = 0; L < 2; L++) {
        int base = 6 + L * 8;
        const float* edge = (const float*)d_in[base + 0];
        const float* lng  = (const float*)d_in[base + 1];
        const float* lnb  = (const float*)d_in[base + 2];
        const float* Wc   = (const float*)d_in[base + 3];
        const float* bc   = (const float*)d_in[base + 4];
        const float* Ws   = (const float*)d_in[base + 5];
        const float* bs   = (const float*)d_in[base + 6];
        const float* Wo   = (const float*)d_in[base + 7];

        attn_kernel<<<1024, 256, smem_attn>>>(node, edge, t2, attnb);
        ln_kernel<<<51200 / 8, 256>>>(t2, spatial, lng, lnb, 51200, 1);
        cos_kernel<<<6300, 256>>>(spatial, cosb, t2, t3);
        gemm_tf32<<<gTmp, 256, smem_gemm>>>(t2, Wc, bc, nullptr, nullptr,
                                            t1, 50400, 1);
        gemm_tf32<<<gTmp, 256, smem_gemm>>>(t3, Ws, bs, t1, spatial,
                                            t2, 50400, 2);
        copy_t0_kernel<<<400, 256>>>(spatial, t2);
        ln_kernel<<<51200 / 8, 256>>>(t2, t3, lng, lnb, 51200, 0);
        gemm_tf32<<<gAll, 256, smem_gemm>>>(t3, Wo, nullptr, node, nullptr,
                                            node, 51200, 3);
    }

    gemm_tf32<<<gAll, 256, smem_gemm>>>(node, out_W, out_b, nullptr, nullptr,
                                        (float*)d_out, 51200, 0);

    long long need = OUT_ELEMS + ATTN_ELEMS + COS_ELEMS;
    if ((long long)out_size >= need) {
        cudaMemcpyAsync((float*)d_out + OUT_ELEMS, attnb,
                        ATTN_ELEMS * sizeof(float), cudaMemcpyDeviceToDevice);
        cudaMemcpyAsync((float*)d_out + OUT_ELEMS + ATTN_ELEMS, cosb,
                        COS_ELEMS * sizeof(float), cudaMemcpyDeviceToDevice);
    }
}

// round 4
// speedup vs baseline: 2.9965x; 1.7182x over previous
#include <cuda_runtime.h>
#include <cuda_fp16.h>
#include <cstdint>

// ---------------------------------------------------------------------------
// Problem: B=16, T=64, N=49(+1)=50 nodes, D=H=512, WIN=7
// ---------------------------------------------------------------------------
#define NEGBIG (-1e9f)

static const long long OUT_ELEMS  = 51200LL * 512;
static const long long ATTN_ELEMS = 1024LL * 2500;
static const long long COS_ELEMS  = 50400LL;

// ---------------------------------------------------------------------------
// Device scratch
// ---------------------------------------------------------------------------
__device__ float  g_node[51200 * 512];
__device__ float  g_spatial[51200 * 512];
__device__ float  g_t1[51200 * 512];
__device__ float  g_t2[51200 * 512];
__device__ float  g_attn[1024 * 2500];
__device__ float  g_cos[50400];
__device__ __half g_hA[51200 * 512];     // concat out (half)
__device__ __half g_hc[50400 * 512];     // cos*prev
__device__ __half g_hs[50400 * 512];     // (1-cos)*cur
__device__ __half g_ht3[51200 * 512];    // ln(out_pre)
__device__ __half g_hnode[51200 * 512];  // node (half mirror)
__device__ __half g_wh[8 * 512 * 512];   // half weights

// ---------------------------------------------------------------------------
// helpers
// ---------------------------------------------------------------------------
__device__ __forceinline__ uint32_t smem_u32(const void* p) {
    uint32_t a;
    asm("{ .reg .u64 t; cvta.to.shared.u64 t, %1; cvt.u32.u64 %0, t; }"
        : "=r"(a) : "l"(p));
    return a;
}
__device__ __forceinline__ uint32_t sw128(uint32_t off) {
    return off ^ ((off >> 3) & 0x70);
}
__device__ __forceinline__ void cp16(uint32_t dst, const void* src) {
    asm volatile("cp.async.cg.shared.global [%0], [%1], 16;\n"
                 :: "r"(dst), "l"(src));
}
__device__ __forceinline__ void cp_commit() {
    asm volatile("cp.async.commit_group;\n" ::: "memory");
}
__device__ __forceinline__ void cp_wait1() {
    asm volatile("cp.async.wait_group 1;\n" ::: "memory");
}
__device__ __forceinline__ void ldm_x4(uint32_t r[4], uint32_t addr) {
    asm volatile("ldmatrix.sync.aligned.m8n8.x4.shared.b16 {%0,%1,%2,%3}, [%4];"
                 : "=r"(r[0]), "=r"(r[1]), "=r"(r[2]), "=r"(r[3]) : "r"(addr));
}
__device__ __forceinline__ void mma_fp16(
    float c[4], uint32_t a0, uint32_t a1, uint32_t a2, uint32_t a3,
    uint32_t b0, uint32_t b1)
{
    asm volatile(
        "mma.sync.aligned.m16n8k16.row.col.f32.f16.f16.f32 "
        "{%0,%1,%2,%3}, {%4,%5,%6,%7}, {%8,%9}, {%0,%1,%2,%3};\n"
        : "+f"(c[0]), "+f"(c[1]), "+f"(c[2]), "+f"(c[3])
        : "r"(a0), "r"(a1), "r"(a2), "r"(a3), "r"(b0), "r"(b1));
}

// ---------------------------------------------------------------------------
// weights -> half
// ---------------------------------------------------------------------------
__global__ __launch_bounds__(256) void wround_kernel(
    const float* __restrict__ src, __half* __restrict__ dst)
{
    int i = blockIdx.x * 256 + threadIdx.x;   // 65536 float4 chunks
    float4 v = ((const float4*)src)[i];
    __half2* d = (__half2*)dst;
    d[i * 2 + 0] = __floats2half2_rn(v.x, v.y);
    d[i * 2 + 1] = __floats2half2_rn(v.z, v.w);
}

// ---------------------------------------------------------------------------
// concat(visual, audio) -> half [51200, 512]
// ---------------------------------------------------------------------------
__global__ __launch_bounds__(256) void concat_kernel(
    const float* __restrict__ vis, const float* __restrict__ aud,
    __half* __restrict__ out)
{
    long long idx = (long long)blockIdx.x * 256 + threadIdx.x;
    if (idx >= (long long)51200 * 128) return;
    long long r = idx >> 7;
    int hv = (int)(idx & 127);
    int bt = (int)(r / 50), i = (int)(r % 50);
    float4 v;
    if (i < 49)
        v = ((const float4*)vis)[((long long)bt * 49 + i) * 128 + hv];
    else
        v = ((const float4*)aud)[(long long)bt * 128 + hv];
    __half2* d = (__half2*)out;
    d[idx * 2 + 0] = __floats2half2_rn(v.x, v.y);
    d[idx * 2 + 1] = __floats2half2_rn(v.z, v.w);
}

// ---------------------------------------------------------------------------
// fp16 tensor-core NT GEMM: C = epilogue(A[M,512] @ W[512,512]^T)
// CTA tile 128x128, k-tile 64, 3-stage cp.async pipeline, ldmatrix fragments.
// warp grid 2x4, warp tile 64x32.
// mode 0: C = acc + bias
// mode 1: C = relu(acc + bias)
// mode 2: scatter g=row(b,tq+1,i): C[g] = add2[g] + add1[m] + relu(acc+bias)
// mode 3: C = add1[m] + relu(acc), also writes half mirror Ch
// ---------------------------------------------------------------------------
#define STAGE_BYTES 32768          // A 128*128B + B 128*128B
#define GEMM_SMEM   (3 * STAGE_BYTES)

__global__ __launch_bounds__(256) void gemm_fp16(
    const __half* __restrict__ A, const __half* __restrict__ W,
    const float* __restrict__ bias, const float* __restrict__ add1,
    const float* __restrict__ add2, float* __restrict__ C,
    __half* __restrict__ Ch, int M, int mode)
{
    extern __shared__ char smem[];
    const uint32_t sb = smem_u32(smem);

    const int tid = threadIdx.x;
    const int wid = tid >> 5, lane = tid & 31;
    const int wm = wid >> 2, wn = wid & 3;
    const int g = lane >> 2, t = lane & 3;
    const int m0 = blockIdx.y * 128;
    const int n0 = blockIdx.x * 128;

    float acc[4][4][4];
#pragma unroll
    for (int mf = 0; mf < 4; mf++)
#pragma unroll
        for (int nf = 0; nf < 4; nf++)
#pragma unroll
            for (int q = 0; q < 4; q++) acc[mf][nf][q] = 0.f;

    auto load_stage = [&](int s) {
        const int buf = s % 3;
        const uint32_t ab = sb + buf * STAGE_BYTES;
        const uint32_t bb = ab + 16384;
        const int k0 = s * 64;
#pragma unroll
        for (int i = 0; i < 8; i++) {
            int o = tid + i * 256;            // 0..2047
            int oo = o & 1023;
            int row = oo >> 3, c = oo & 7;
            uint32_t off = sw128((uint32_t)(row * 128 + c * 16));
            if (o < 1024) {
                int sr = m0 + row; if (sr > M - 1) sr = M - 1;
                cp16(ab + off, A + (long long)sr * 512 + k0 + c * 8);
            } else {
                cp16(bb + off, W + (long long)(n0 + row) * 512 + k0 + c * 8);
            }
        }
    };

    load_stage(0); cp_commit();
    load_stage(1); cp_commit();

    // fragment address offsets (constant per thread)
    const int a_row = (lane & 15);
    const int a_c16 = (lane >> 4);
    const int b_row = ((lane >> 4) << 3) + (lane & 7);
    const int b_c16 = ((lane >> 3) & 1);

    for (int s = 0; s < 8; s++) {
        cp_wait1();
        __syncthreads();
        const int buf = s % 3;
        const uint32_t ab = sb + buf * STAGE_BYTES;
        const uint32_t bb = ab + 16384;

#pragma unroll
        for (int ks = 0; ks < 4; ks++) {
            uint32_t af[4][4], bf[2][4];
#pragma unroll
            for (int mf = 0; mf < 4; mf++) {
                int m = wm * 64 + mf * 16 + a_row;
                ldm_x4(af[mf], ab + sw128((uint32_t)(m * 128 + ks * 32 + a_c16 * 16)));
            }
#pragma unroll
            for (int np = 0; np < 2; np++) {
                int n = wn * 32 + np * 16 + b_row;
                ldm_x4(bf[np], bb + sw128((uint32_t)(n * 128 + ks * 32 + b_c16 * 16)));
            }
#pragma unroll
            for (int mf = 0; mf < 4; mf++) {
                mma_fp16(acc[mf][0], af[mf][0], af[mf][1], af[mf][2], af[mf][3],
                         bf[0][0], bf[0][1]);
                mma_fp16(acc[mf][1], af[mf][0], af[mf][1], af[mf][2], af[mf][3],
                         bf[0][2], bf[0][3]);
                mma_fp16(acc[mf][2], af[mf][0], af[mf][1], af[mf][2], af[mf][3],
                         bf[1][0], bf[1][1]);
                mma_fp16(acc[mf][3], af[mf][0], af[mf][1], af[mf][2], af[mf][3],
                         bf[1][2], bf[1][3]);
            }
        }
        if (s + 2 < 8) load_stage(s + 2);
        cp_commit();
    }

    // ---------------- epilogue ----------------
#pragma unroll
    for (int mf = 0; mf < 4; mf++) {
#pragma unroll
        for (int h = 0; h < 2; h++) {
            int m = m0 + wm * 64 + mf * 16 + g + h * 8;
            if (m >= M) continue;
            long long orow;
            if (mode == 2) {
                int b_ = m / 3150, tq = (m / 50) % 63, i_ = m % 50;
                orow = ((long long)(b_ * 64 + tq + 1) * 50 + i_) * 512;
            } else {
                orow = (long long)m * 512;
            }
            long long arow = (long long)m * 512;
#pragma unroll
            for (int nf = 0; nf < 4; nf++) {
                int n = n0 + wn * 32 + nf * 8 + t * 2;
                float v0 = acc[mf][nf][h * 2 + 0];
                float v1 = acc[mf][nf][h * 2 + 1];
                float o0, o1;
                if (mode == 0) {
                    o0 = v0 + bias[n]; o1 = v1 + bias[n + 1];
                } else if (mode == 1) {
                    o0 = fmaxf(v0 + bias[n], 0.f);
                    o1 = fmaxf(v1 + bias[n + 1], 0.f);
                } else if (mode == 2) {
                    o0 = add2[orow + n]     + add1[arow + n]     + fmaxf(v0 + bias[n], 0.f);
                    o1 = add2[orow + n + 1] + add1[arow + n + 1] + fmaxf(v1 + bias[n + 1], 0.f);
                } else {
                    o0 = add1[arow + n]     + fmaxf(v0, 0.f);
                    o1 = add1[arow + n + 1] + fmaxf(v1, 0.f);
                }
                *(float2*)(C + orow + n) = make_float2(o0, o1);
                if (mode == 3)
                    *(__half2*)(Ch + orow + n) = __floats2half2_rn(o0, o1);
            }
        }
    }
}

// ---------------------------------------------------------------------------
// Fused attention for one (b,t): Gram trick + mask + softmax + aggregation
// ---------------------------------------------------------------------------
#define ATTN_SMEM_FLOATS (52*512 + 3*512 + 52*52 + 6*52 + 8)

__global__ __launch_bounds__(256) void attn_kernel(
    const float* __restrict__ x, const float* __restrict__ edge,
    float* __restrict__ y_out, float* __restrict__ attn_out)
{
    extern __shared__ float sm[];
    float* xs  = sm;
    float* es  = xs + 52 * 512;
    float* G   = es + 3 * 512;
    float* rq  = G + 52 * 52;
    float* rk0 = rq + 52;
    float* rk1 = rk0 + 52;
    float* d0  = rk1 + 52;
    float* d1  = d0 + 52;
    float* d2  = d1 + 52;
    float* sc  = d2 + 52;

    const int bt = blockIdx.x;
    const int tid = threadIdx.x;
    const float* xg = x + (long long)bt * 50 * 512;

    for (int idx = tid; idx < 50 * 128; idx += 256)
        ((float4*)xs)[idx] = ((const float4*)xg)[idx];
    for (int idx = tid; idx < 2 * 128; idx += 256)
        ((float4*)xs)[50 * 128 + idx] = make_float4(0.f, 0.f, 0.f, 0.f);
    for (int idx = tid; idx < 3 * 128; idx += 256)
        ((float4*)es)[idx] = ((const float4*)edge)[idx];
    __syncthreads();

    if (tid < 169) {
        int i0 = (tid / 13) * 4, j0 = (tid % 13) * 4;
        float acc[4][4];
#pragma unroll
        for (int u = 0; u < 4; u++)
#pragma unroll
            for (int v = 0; v < 4; v++) acc[u][v] = 0.f;
        const float4* xi0 = (const float4*)(xs + (i0 + 0) * 512);
        const float4* xi1 = (const float4*)(xs + (i0 + 1) * 512);
        const float4* xi2 = (const float4*)(xs + (i0 + 2) * 512);
        const float4* xi3 = (const float4*)(xs + (i0 + 3) * 512);
        const float4* xj0 = (const float4*)(xs + (j0 + 0) * 512);
        const float4* xj1 = (const float4*)(xs + (j0 + 1) * 512);
        const float4* xj2 = (const float4*)(xs + (j0 + 2) * 512);
        const float4* xj3 = (const float4*)(xs + (j0 + 3) * 512);
#pragma unroll 2
        for (int k = 0; k < 128; k++) {
            float4 A0 = xi0[k], A1 = xi1[k], A2 = xi2[k], A3 = xi3[k];
            float4 B0 = xj0[k], B1 = xj1[k], B2 = xj2[k], B3 = xj3[k];
#define GACC(u,v,Au,Bv) acc[u][v] += Au.x*Bv.x + Au.y*Bv.y + Au.z*Bv.z + Au.w*Bv.w;
            GACC(0,0,A0,B0) GACC(0,1,A0,B1) GACC(0,2,A0,B2) GACC(0,3,A0,B3)
            GACC(1,0,A1,B0) GACC(1,1,A1,B1) GACC(1,2,A1,B2) GACC(1,3,A1,B3)
            GACC(2,0,A2,B0) GACC(2,1,A2,B1) GACC(2,2,A2,B2) GACC(2,3,A2,B3)
            GACC(3,0,A3,B0) GACC(3,1,A3,B1) GACC(3,2,A3,B2) GACC(3,3,A3,B3)
#undef GACC
        }
#pragma unroll
        for (int u = 0; u < 4; u++)
#pragma unroll
            for (int v = 0; v < 4; v++)
                G[(i0 + u) * 52 + (j0 + v)] = acc[u][v];
    }
    __syncthreads();

    if (tid < 150) {
        int kk = tid % 3, i = tid / 3;
        const float4* ev = (const float4*)(es + kk * 512);
        const float4* xv = (const float4*)(xs + i * 512);
        float s = 0.f;
        for (int k = 0; k < 128; k++) {
            float4 e4 = ev[k], x4 = xv[k];
            s += e4.x * x4.x + e4.y * x4.y + e4.z * x4.z + e4.w * x4.w;
        }
        (kk == 0 ? d0 : (kk == 1 ? d1 : d2))[i] = s;
    } else if (tid >= 160 && tid < 163) {
        int kk = tid - 160;
        const float4* ev = (const float4*)(es + kk * 512);
        float s = 0.f;
        for (int k = 0; k < 128; k++) {
            float4 e4 = ev[k];
            s += e4.x * e4.x + e4.y * e4.y + e4.z * e4.z + e4.w * e4.w;
        }
        sc[kk] = s;
    }
    __syncthreads();

    if (tid < 50) {
        float gd = G[tid * 53];
        rq[tid]  = 1.f / fmaxf(sqrtf(gd), 1e-12f);
        rk0[tid] = 1.f / fmaxf(sqrtf(gd + 2.f * d0[tid] + sc[0]), 1e-12f);
        rk1[tid] = 1.f / fmaxf(sqrtf(gd + 2.f * d1[tid] + sc[1]), 1e-12f);
    } else if (tid == 50) {
        sc[3] = 1.f / fmaxf(sqrtf(G[49 * 53] + 2.f * d2[49] + sc[2]), 1e-12f);
    }
    __syncthreads();

    const float rk2  = sc[3];
    const float d149 = d1[49];
    const float rq49 = rq[49];

    for (int p = tid; p < 2500; p += 256) {
        int i = p / 50, j = p - i * 50;
        float v;
        if (i == j)        v = NEGBIG;
        else if (j == 49)  v = (G[i * 52 + 49] + d2[i]) * rq[i] * rk2;
        else if (i == 49)  v = (G[49 * 52 + j] + d149) * rq49 * rk1[j];
        else {
            int qr = i / 7, qc = i - qr * 7;
            int kr = j / 7, kc = j - kr * 7;
            int r0 = qr - 1; if (r0 < 0) r0 = 0;
            int c0 = qc - 1; if (c0 < 0) c0 = 0; if (c0 > 4) c0 = 4;
            bool ok = (kr >= r0) && (kr <= r0 + 2) && (kc >= c0) && (kc <= c0 + 2);
            v = ok ? (G[i * 52 + j] + d0[i]) * rq[i] * rk0[j] : NEGBIG;
        }
        G[i * 52 + j] = v;
    }
    __syncthreads();

    if (tid < 50) {
        float* row = G + tid * 52;
        float mx = -3.4e38f;
        for (int j = 0; j < 50; j++) mx = fmaxf(mx, row[j]);
        float s = 0.f;
        for (int j = 0; j < 50; j++) { float e = expf(row[j] - mx); row[j] = e; s += e; }
        float inv = 1.f / s;
        for (int j = 0; j < 50; j++) row[j] *= inv;
    }
    __syncthreads();

    for (int p = tid; p < 2500; p += 256)
        attn_out[(long long)bt * 2500 + p] = G[(p / 50) * 52 + (p % 50)];

    for (int w = tid; w < 13 * 128; w += 256) {
        int it = w >> 7, hv = w & 127;
        int i0 = it * 4;
        float4 acc[4];
#pragma unroll
        for (int u = 0; u < 4; u++) acc[u] = make_float4(0.f, 0.f, 0.f, 0.f);
        for (int j = 0; j < 50; j++) {
            float4 xv = ((const float4*)(xs + j * 512))[hv];
            float a0 = G[(i0 + 0) * 52 + j];
            float a1 = G[(i0 + 1) * 52 + j];
            float a2 = G[(i0 + 2) * 52 + j];
            float a3 = G[(i0 + 3) * 52 + j];
            acc[0].x += a0 * xv.x; acc[0].y += a0 * xv.y; acc[0].z += a0 * xv.z; acc[0].w += a0 * xv.w;
            acc[1].x += a1 * xv.x; acc[1].y += a1 * xv.y; acc[1].z += a1 * xv.z; acc[1].w += a1 * xv.w;
            acc[2].x += a2 * xv.x; acc[2].y += a2 * xv.y; acc[2].z += a2 * xv.z; acc[2].w += a2 * xv.w;
            acc[3].x += a3 * xv.x; acc[3].y += a3 * xv.y; acc[3].z += a3 * xv.z; acc[3].w += a3 * xv.w;
        }
        float4 e2v = ((const float4*)(es + 1024))[hv];
#pragma unroll
        for (int u = 0; u < 4; u++) {
            int i = i0 + u;
            if (i >= 50) break;
            float aL = G[i * 52 + 49];
            float4 esel = ((const float4*)(es + (i < 49 ? 0 : 512)))[hv];
            float4 xr = ((const float4*)(xs + i * 512))[hv];
            float w1 = 1.f - aL;
            float4 o;
            o.x = acc[u].x + w1 * esel.x + aL * e2v.x + xr.x;
            o.y = acc[u].y + w1 * esel.y + aL * e2v.y + xr.y;
            o.z = acc[u].z + w1 * esel.z + aL * e2v.z + xr.z;
            o.w = acc[u].w + w1 * esel.w + aL * e2v.w + xr.w;
            ((float4*)(y_out + ((long long)bt * 50 + i) * 512))[hv] = o;
        }
    }
}

// ---------------------------------------------------------------------------
// LayerNorm (warp per 512-row); writes fp32 (if outf) and/or half (if outh)
// ---------------------------------------------------------------------------
__global__ __launch_bounds__(256) void ln_kernel(
    const float* __restrict__ in, float* __restrict__ outf,
    __half* __restrict__ outh,
    const float* __restrict__ g, const float* __restrict__ b,
    int rows, int do_relu)
{
    int warp = (blockIdx.x * 256 + threadIdx.x) >> 5;
    int lane = threadIdx.x & 31;
    if (warp >= rows) return;
    const float4* ip = (const float4*)(in + (long long)warp * 512);
    float4 v[4];
    float s = 0.f;
#pragma unroll
    for (int q = 0; q < 4; q++) {
        v[q] = ip[lane + 32 * q];
        s += v[q].x + v[q].y + v[q].z + v[q].w;
    }
#pragma unroll
    for (int off = 16; off; off >>= 1) s += __shfl_xor_sync(0xffffffffu, s, off);
    float mean = s * (1.f / 512.f);
    float ss = 0.f;
#pragma unroll
    for (int q = 0; q < 4; q++) {
        float dx = v[q].x - mean, dy = v[q].y - mean, dz = v[q].z - mean, dw = v[q].w - mean;
        ss += dx * dx + dy * dy + dz * dz + dw * dw;
    }
#pragma unroll
    for (int off = 16; off; off >>= 1) ss += __shfl_xor_sync(0xffffffffu, ss, off);
    float inv = rsqrtf(ss * (1.f / 512.f) + 1e-5f);
    const float4* gp = (const float4*)g;
    const float4* bp = (const float4*)b;
#pragma unroll
    for (int q = 0; q < 4; q++) {
        int c = lane + 32 * q;
        float4 gv = gp[c], bv = bp[c], o;
        o.x = (v[q].x - mean) * inv * gv.x + bv.x;
        o.y = (v[q].y - mean) * inv * gv.y + bv.y;
        o.z = (v[q].z - mean) * inv * gv.z + bv.z;
        o.w = (v[q].w - mean) * inv * gv.w + bv.w;
        if (do_relu) {
            o.x = fmaxf(o.x, 0.f); o.y = fmaxf(o.y, 0.f);
            o.z = fmaxf(o.z, 0.f); o.w = fmaxf(o.w, 0.f);
        }
        if (outf) ((float4*)(outf + (long long)warp * 512))[c] = o;
        if (outh) {
            __half2* hp = (__half2*)(outh + (long long)warp * 512);
            hp[c * 2 + 0] = __floats2half2_rn(o.x, o.y);
            hp[c * 2 + 1] = __floats2half2_rn(o.z, o.w);
        }
    }
}

// ---------------------------------------------------------------------------
// cos similarity + half GEMM inputs: hc = cos*prev, hs = (1-cos)*cur
// ---------------------------------------------------------------------------
__global__ __launch_bounds__(256) void cos_kernel(
    const float* __restrict__ spatial, float* __restrict__ cosv,
    __half* __restrict__ hc, __half* __restrict__ hs)
{
    int warp = (blockIdx.x * 256 + threadIdx.x) >> 5;
    int lane = threadIdx.x & 31;
    if (warp >= 50400) return;
    int i = warp % 50;
    int tq = (warp / 50) % 63;
    int b_ = warp / 3150;
    long long cur_off  = (((long long)b_ * 64 + tq + 1) * 50 + i) * 512;
    long long prev_off = (((long long)b_ * 64 + tq) * 50 + i) * 512;
    const float4* cp = (const float4*)(spatial + cur_off);
    const float4* pp = (const float4*)(spatial + prev_off);
    float4 cb[4], pb[4];
    float dt = 0.f, na = 0.f, nb = 0.f;
#pragma unroll
    for (int q = 0; q < 4; q++) {
        cb[q] = cp[lane + 32 * q];
        pb[q] = pp[lane + 32 * q];
        dt += cb[q].x * pb[q].x + cb[q].y * pb[q].y + cb[q].z * pb[q].z + cb[q].w * pb[q].w;
        na += cb[q].x * cb[q].x + cb[q].y * cb[q].y + cb[q].z * cb[q].z + cb[q].w * cb[q].w;
        nb += pb[q].x * pb[q].x + pb[q].y * pb[q].y + pb[q].z * pb[q].z + pb[q].w * pb[q].w;
    }
#pragma unroll
    for (int off = 16; off; off >>= 1) {
        dt += __shfl_xor_sync(0xffffffffu, dt, off);
        na += __shfl_xor_sync(0xffffffffu, na, off);
        nb += __shfl_xor_sync(0xffffffffu, nb, off);
    }
    float cv = dt / (fmaxf(sqrtf(na), 1e-8f) * fmaxf(sqrtf(nb), 1e-8f));
    if (lane == 0) cosv[warp] = cv;
    __half2* hcp = (__half2*)(hc + (long long)warp * 512);
    __half2* hsp = (__half2*)(hs + (long long)warp * 512);
    float w1 = 1.f - cv;
#pragma unroll
    for (int q = 0; q < 4; q++) {
        int c = lane + 32 * q;
        hcp[c * 2 + 0] = __floats2half2_rn(cv * pb[q].x, cv * pb[q].y);
        hcp[c * 2 + 1] = __floats2half2_rn(cv * pb[q].z, cv * pb[q].w);
        hsp[c * 2 + 0] = __floats2half2_rn(w1 * cb[q].x, w1 * cb[q].y);
        hsp[c * 2 + 1] = __floats2half2_rn(w1 * cb[q].z, w1 * cb[q].w);
    }
}

// ---------------------------------------------------------------------------
// copy t=0 rows of spatial into out_pre buffer
// ---------------------------------------------------------------------------
__global__ __launch_bounds__(256) void copy_t0_kernel(
    const float* __restrict__ src, float* __restrict__ dst)
{
    int idx = blockIdx.x * 256 + threadIdx.x;
    if (idx >= 800 * 128) return;
    int r = idx >> 7, hv = idx & 127;
    int b_ = r / 50, i = r % 50;
    long long row = ((long long)b_ * 64) * 50 + i;
    ((float4*)(dst + row * 512))[hv] = ((const float4*)(src + row * 512))[hv];
}

// ---------------------------------------------------------------------------
// Host launcher
// ---------------------------------------------------------------------------
extern "C" void kernel_launch(void* const* d_in, const int* in_sizes, int n_in,
                              void* d_out, int out_size)
{
    const float* visual = (const float*)d_in[0];
    const float* audio  = (const float*)d_in[1];
    const float* in_W   = (const float*)d_in[2];
    const float* in_b   = (const float*)d_in[3];
    const float* out_W  = (const float*)d_in[4];
    const float* out_b  = (const float*)d_in[5];

    float *node, *spatial, *t1, *t2, *attnb, *cosb;
    __half *hA, *hc, *hs, *ht3, *hnode, *wh;
    cudaGetSymbolAddress((void**)&node,    g_node);
    cudaGetSymbolAddress((void**)&spatial, g_spatial);
    cudaGetSymbolAddress((void**)&t1,      g_t1);
    cudaGetSymbolAddress((void**)&t2,      g_t2);
    cudaGetSymbolAddress((void**)&attnb,   g_attn);
    cudaGetSymbolAddress((void**)&cosb,    g_cos);
    cudaGetSymbolAddress((void**)&hA,      g_hA);
    cudaGetSymbolAddress((void**)&hc,      g_hc);
    cudaGetSymbolAddress((void**)&hs,      g_hs);
    cudaGetSymbolAddress((void**)&ht3,     g_ht3);
    cudaGetSymbolAddress((void**)&hnode,   g_hnode);
    cudaGetSymbolAddress((void**)&wh,      g_wh);

    const int smem_attn = ATTN_SMEM_FLOATS * 4;
    cudaFuncSetAttribute(attn_kernel,
                         cudaFuncAttributeMaxDynamicSharedMemorySize, smem_attn);
    cudaFuncSetAttribute(gemm_fp16,
                         cudaFuncAttributeMaxDynamicSharedMemorySize, GEMM_SMEM);

    // weights -> half, once per call
    const float* wsrc[8] = {
        in_W, (const float*)d_in[9], (const float*)d_in[11], (const float*)d_in[13],
        (const float*)d_in[17], (const float*)d_in[19], (const float*)d_in[21], out_W };
    for (int i = 0; i < 8; i++)
        wround_kernel<<<256, 256>>>(wsrc[i], wh + (long long)i * 262144);

    concat_kernel<<<25600, 256>>>(visual, audio, hA);
    dim3 gAll(4, 400);
    dim3 gTmp(4, 394);
    gemm_fp16<<<gAll, 256, GEMM_SMEM>>>(hA, wh + 0 * 262144, in_b,
                                        nullptr, nullptr, node, nullptr,
                                        51200, 0);

    for (int L = 0; L < 2; L++) {
        int base = 6 + L * 8;
        const float* edge = (const float*)d_in[base + 0];
        const float* lng  = (const float*)d_in[base + 1];
        const float* lnb  = (const float*)d_in[base + 2];
        const float* bc   = (const float*)d_in[base + 4];
        const float* bs   = (const float*)d_in[base + 6];
        const __half* wc  = wh + (long long)(1 + L * 3) * 262144;
        const __half* ws  = wh + (long long)(2 + L * 3) * 262144;
        const __half* wo  = wh + (long long)(3 + L * 3) * 262144;

        attn_kernel<<<1024, 256, smem_attn>>>(node, edge, t2, attnb);
        ln_kernel<<<6400, 256>>>(t2, spatial, nullptr, lng, lnb, 51200, 1);
        cos_kernel<<<6300, 256>>>(spatial, cosb, hc, hs);
        gemm_fp16<<<gTmp, 256, GEMM_SMEM>>>(hc, wc, bc, nullptr, nullptr,
                                            t1, nullptr, 50400, 1);
        gemm_fp16<<<gTmp, 256, GEMM_SMEM>>>(hs, ws, bs, t1, spatial,
                                            t2, nullptr, 50400, 2);
        copy_t0_kernel<<<400, 256>>>(spatial, t2);
        ln_kernel<<<6400, 256>>>(t2, nullptr, ht3, lng, lnb, 51200, 0);
        gemm_fp16<<<gAll, 256, GEMM_SMEM>>>(ht3, wo, nullptr, node, nullptr,
                                            node, hnode, 51200, 3);
    }

    gemm_fp16<<<gAll, 256, GEMM_SMEM>>>(hnode, wh + 7LL * 262144, out_b,
                                        nullptr, nullptr, (float*)d_out,
                                        nullptr, 51200, 0);

    long long need = OUT_ELEMS + ATTN_ELEMS + COS_ELEMS;
    if ((long long)out_size >= need) {
        cudaMemcpyAsync((float*)d_out + OUT_ELEMS, attnb,
                        ATTN_ELEMS * sizeof(float), cudaMemcpyDeviceToDevice);
        cudaMemcpyAsync((float*)d_out + OUT_ELEMS + ATTN_ELEMS, cosb,
                        COS_ELEMS * sizeof(float), cudaMemcpyDeviceToDevice);
    }
}